// round 1
// baseline (speedup 1.0000x reference)
#include <cuda_runtime.h>
#include <math.h>

// Accumulator: acc[bq][n], bq = b*2 + q, capacity 2M floats (need 32*30000 = 960K).
// Static __device__ arrays — no allocation anywhere, per harness rules.
#define ACC_CAP (1 << 21)
#define W_CAP   (1 << 16)
__device__ float g_acc[ACC_CAP];
__device__ float g_W[W_CAP];

// K0: zero accumulator + build W[bq][t] = sum_d rel_emb[r_index[bq]][d] * rel_proj[t][d] * w_out[d]
__global__ void k_init(const int* __restrict__ r_index,
                       const float* __restrict__ rel_emb,
                       const float* __restrict__ rel_proj,
                       const float* __restrict__ w_out,
                       int nBQ, int R, int D, int accN)
{
    int stride = gridDim.x * blockDim.x;
    int i = blockIdx.x * blockDim.x + threadIdx.x;
    for (int j = i; j < accN; j += stride) g_acc[j] = 0.0f;
    int nW = nBQ * R;
    for (int j = i; j < nW; j += stride) {
        int bq = j / R;
        int t  = j - bq * R;
        int r  = r_index[bq];
        const float* a = rel_emb  + (size_t)r * D;
        const float* p = rel_proj + (size_t)t * D;
        float s = 0.0f;
        #pragma unroll 8
        for (int d = 0; d < D; d++) s += a[d] * p[d] * w_out[d];
        g_W[j] = s;
    }
}

// K1: per-edge scatter. Only edges whose src matches one of the nBQ query
// entities contribute; edge_type is loaded lazily (only on match).
__global__ void k_scatter(const int* __restrict__ e_index,
                          const int* __restrict__ edge_index,
                          const int* __restrict__ edge_type,
                          int E, int nBQ, int R, int N)
{
    __shared__ int s_e[64];
    int tid = threadIdx.x;
    if (tid < nBQ) s_e[tid] = e_index[tid];
    __syncthreads();

    int e = blockIdx.x * blockDim.x + tid;
    if (e >= E) return;

    int src = edge_index[e];        // row 0 of (2, E)
    int t = -1;
    for (int bq = 0; bq < nBQ; bq++) {
        if (src == s_e[bq]) {
            if (t < 0) t = edge_type[e];
            int dst = edge_index[E + e];   // row 1 of (2, E)
            atomicAdd(&g_acc[(size_t)bq * N + dst], g_W[bq * R + t]);
        }
    }
}

// K2: out[b*N+n] = log((sig(a1)*sig(a2)+eps) / (1 - sig(a1)*sig(a2) + eps))
__global__ void k_final(float* __restrict__ out, int B, int N)
{
    int i = blockIdx.x * blockDim.x + threadIdx.x;
    int total = B * N;
    if (i >= total) return;
    int b = i / N;
    int n = i - b * N;
    float a1 = g_acc[(size_t)(2 * b)     * N + n];
    float a2 = g_acc[(size_t)(2 * b + 1) * N + n];
    float t1 = 1.0f / (1.0f + __expf(-a1));
    float t2 = 1.0f / (1.0f + __expf(-a2));
    float tp = t1 * t2;
    const float EPS = 1e-10f;
    out[i] = __logf((tp + EPS) / (1.0f - tp + EPS));
}

extern "C" void kernel_launch(void* const* d_in, const int* in_sizes, int n_in,
                              void* d_out, int out_size)
{
    // Input order: e_index, r_index, edge_index, edge_type, [num_nodes], rel_emb, rel_proj, w_out
    const int* e_index    = (const int*)d_in[0];
    const int* r_index    = (const int*)d_in[1];
    const int* edge_index = (const int*)d_in[2];
    const int* edge_type  = (const int*)d_in[3];
    int off = (n_in >= 8) ? 5 : 4;   // skip scalar num_nodes input if present
    const float* rel_emb  = (const float*)d_in[off];
    const float* rel_proj = (const float*)d_in[off + 1];
    const float* w_out    = (const float*)d_in[off + 2];

    int nBQ = in_sizes[0];               // B*2 (e_index is [B,2])
    int B   = nBQ / 2;
    int E   = in_sizes[3];               // edge_type is [E]
    int D   = in_sizes[off + 2];         // w_out is [D]
    int R   = in_sizes[off] / D;         // rel_emb is [R, D]
    int N   = out_size / B;              // output is [B, N]

    int accN = nBQ * N;

    const int TPB = 256;
    int gridInit  = (accN + TPB - 1) / TPB;
    int gridScat  = (E + TPB - 1) / TPB;
    int gridFinal = (B * N + TPB - 1) / TPB;

    k_init   <<<gridInit,  TPB>>>(r_index, rel_emb, rel_proj, w_out, nBQ, R, D, accN);
    k_scatter<<<gridScat,  TPB>>>(e_index, edge_index, edge_type, E, nBQ, R, N);
    k_final  <<<gridFinal, TPB>>>((float*)d_out, B, N);
}